// round 16
// baseline (speedup 1.0000x reference)
#include <cuda_runtime.h>
#include <cuda_bf16.h>
#include <cstdint>

// HungarianMatcher cost computation, block-diagonal only.
// Shapes: BS=16, Q=1000, NC=80, T=100, NI=8
// Output: C_diag (BS,Q,T) followed by ioa_diag (BS,Q,NI), f32.
//
// Phase 1: dense (2*focal + 2) table for the block's QPB x NC tile (coalesced,
//          5 passes, refactored: cost2 = r^2*(0.5*e^2*L - 1.5*(x+L)) + 2);
//          raw pred boxes to smem; ioa lanes finish their output here.
// Phase 2: C-only hot loop, software-pipelined: the two per-iteration LDS
//          (pred-box bcast + class gather) are prefetched one iteration ahead
//          so their 29-cyc latency is off the dependency-chain head.

#define BSZ 16
#define QN  1000
#define NC  80
#define TN  100
#define NIN 8
#define QPB 8    // q rows per block; 125 blocks cover Q=1000 exactly

// single-MUFU approximate reciprocal (~1 ulp; tolerance is 1e-3)
__device__ __forceinline__ float frcp(float x) {
    float y;
    asm("rcp.approx.ftz.f32 %0, %1;" : "=f"(y) : "f"(x));
    return y;
}
__device__ __forceinline__ float flg2(float x) {
    float y;
    asm("lg2.approx.ftz.f32 %0, %1;" : "=f"(y) : "f"(x));
    return y;
}

__global__ __launch_bounds__(128, 14)
void matcher_kernel(const float* __restrict__ logits,
                    const float* __restrict__ pboxes,
                    const float* __restrict__ tboxes,
                    const float* __restrict__ iboxes,
                    const float* __restrict__ img,
                    const float* __restrict__ img_tgt,
                    const int*   __restrict__ tids,
                    float* __restrict__ outC,
                    float* __restrict__ outIoa)
{
    __shared__ float  scc[QPB * NC];   // 2*focal cost + 2, [q_local][class]
    __shared__ float4 spq[QPB];        // raw pred boxes

    const int b    = blockIdx.y;
    const int q0   = blockIdx.x * QPB;
    const int lane = threadIdx.x;   // 0..99 -> targets, 100..107 -> ign boxes

    const bool isC   = (lane < TN);
    const bool isIoa = (lane >= TN) && (lane < TN + NIN);

    const float* pbox_base = pboxes + (size_t)(b * QN + q0) * 4;

    // ---------------- phase 1a: dense focal table (all lanes) ---------------
    // p = r = 1/(1+e), 1-p = e*r, L = log(1+e) = lg2(1+e)*ln2
    // cost2 = 2*(pos-neg)+2 = r^2*(0.5*e^2*L - 1.5*(x+L)) + 2
    {
        const float* gl = logits + (size_t)(b * QN + q0) * NC;
        #pragma unroll
        for (int k = 0; k < (QPB * NC) / 128; ++k) {      // exactly 5 passes
            const int idx   = k * 128 + lane;
            const float x   = __ldg(gl + idx);            // fully coalesced
            const float e   = __expf(-x);                 // mul + ex2
            const float s   = 1.f + e;
            const float r   = frcp(s);
            const float lam = flg2(s);
            const float t   = e * e;
            const float a   = t * lam;                    // e^2 * lg2(s)
            const float u   = fmaf(lam, 0.69314718f, x);  // x + L
            const float v   = -1.5f * u;
            const float inner = fmaf(a, 0.34657359f, v);  // 0.5*ln2*a - 1.5u
            const float r2  = r * r;
            scc[idx] = fmaf(r2, inner, 2.f);
        }
    }

    // ---------------- phase 1b: raw pred boxes to smem (lanes 0..QPB-1) -----
    if (lane < QPB) {
        spq[lane] = *reinterpret_cast<const float4*>(pbox_base + lane * 4);
    }

    // ---------------- ioa lanes: full output, straight from gmem ------------
    if (isIoa) {
        const int ii = b * NIN + (lane - TN);
        const float4 ib = *reinterpret_cast<const float4*>(iboxes + ii * 4);
        float* oI = outIoa + (size_t)(b * QN + q0) * NIN + (lane - TN);
        #pragma unroll
        for (int i = 0; i < QPB; ++i) {
            const float4 pb = *reinterpret_cast<const float4*>(pbox_base + i * 4);
            const float ixw = fminf(pb.z, ib.z) - fmaxf(pb.x, ib.x);
            const float iyw = fminf(pb.w, ib.w) - fmaxf(pb.y, ib.y);
            const float inter = fmaxf(ixw, 0.f) * fmaxf(iyw, 0.f);
            const float parea = (pb.z - pb.x) * (pb.w - pb.y);
            oI[i * NIN] = inter * frcp(parea);
        }
    }

    // ---------------- per-lane uniform + target data ------------------------
    // i0..i3 = 5 / img. image_size_xyxy_tgt carries the same [W,H,W,H] per
    // row as image_size_xyxy, so the target normalization reuses i0..i3.
    const float* im = img + b * 4;
    const float i0 = 5.f * frcp(im[0]);
    const float i1 = 5.f * frcp(im[1]);
    const float i2 = 5.f * frcp(im[2]);
    const float i3 = 5.f * frcp(im[3]);

    float tx0 = 0.f, ty0 = 0.f, tx1 = 0.f, ty1 = 0.f;
    float tn0 = 0.f, tn1 = 0.f, tn2 = 0.f, tn3 = 0.f;   // 5 * normalized tgt
    float tw = 0.f, th = 0.f;
    const float* sccls = scc;   // per-lane gather base (scc + cls)

    if (isC) {
        const int ti = b * TN + lane;
        const float4 tb = *reinterpret_cast<const float4*>(tboxes + ti * 4);
        tx0 = tb.x; ty0 = tb.y; tx1 = tb.z; ty1 = tb.w;
        tn0 = tx0 * i0;
        tn1 = ty0 * i1;
        tn2 = tx1 * i2;
        tn3 = ty1 * i3;
        tw = tx1 - tx0;
        th = ty1 - ty0;
        sccls = scc + tids[ti];
    }

    __syncthreads();

    // ---------------- phase 2: C-only hot loop (1-deep smem pipeline) -------
    float* outC_lane = outC + (size_t)(b * QN + q0) * TN + lane;

    if (isC) {
        float4 pb = spq[0];
        float  cc2 = sccls[0];

        #pragma unroll
        for (int i = 0; i < QPB; ++i) {
            // prefetch next iteration's smem operands before computing
            float4 pb_n;
            float  cc2_n;
            if (i + 1 < QPB) {
                pb_n  = spq[i + 1];
                cc2_n = sccls[(i + 1) * NC];
            }

            const float px0 = pb.x, py0 = pb.y, px1 = pb.z, py1 = pb.w;
            const float pw = px1 - px0;
            const float ph = py1 - py0;

            // 5 * L1 bbox cost: |px*ik - tnk| via FFMA, abs-modifier adds
            const float d0 = fmaf(px0, i0, -tn0);
            const float d1 = fmaf(py0, i1, -tn1);
            const float d2 = fmaf(px1, i2, -tn2);
            const float d3 = fmaf(py1, i3, -tn3);
            const float cb5 = (fabsf(d0) + fabsf(d1)) + (fabsf(d2) + fabsf(d3));

            // intersection widths (4 FMNMX + 2 clamps)
            const float ixw = fminf(px1, tx1) - fmaxf(px0, tx0);
            const float iyw = fminf(py1, ty1) - fmaxf(py0, ty0);
            const float inter = fmaxf(ixw, 0.f) * fmaxf(iyw, 0.f);

            // enclosure via min+max identity (no FMNMX, no clamps)
            const float exw = (pw + tw) - ixw;
            const float eyw = (ph + th) - iyw;
            const float enc = exw * eyw;

            // uni = parea + tarea - inter (both areas as FFMA)
            const float uni = fmaf(tw, th, fmaf(pw, ph, -inter));

            // C = cb5 + cc' - 2*(inter*enc + uni^2)/(uni*enc)
            const float M   = fmaf(uni, uni, inter * enc);
            const float n2r = -2.f * frcp(uni * enc);
            outC_lane[i * TN] = fmaf(M, n2r, cb5 + cc2);

            pb  = pb_n;
            cc2 = cc2_n;
        }
    }
}

extern "C" void kernel_launch(void* const* d_in, const int* in_sizes, int n_in,
                              void* d_out, int out_size)
{
    const float* logits  = (const float*)d_in[0];
    const float* pboxes  = (const float*)d_in[1];
    const float* tboxes  = (const float*)d_in[2];
    const float* iboxes  = (const float*)d_in[3];
    const float* img     = (const float*)d_in[4];
    const float* img_tgt = (const float*)d_in[5];
    const int*   tids    = (const int*)d_in[6];

    float* outC   = (float*)d_out;
    float* outIoa = (float*)d_out + (size_t)BSZ * QN * TN;

    dim3 grid(QN / QPB, BSZ);   // 125 x 16 = 2000 blocks
    matcher_kernel<<<grid, 128>>>(logits, pboxes, tboxes, iboxes,
                                  img, img_tgt, tids, outC, outIoa);
}

// round 17
// speedup vs baseline: 1.2143x; 1.2143x over previous
#include <cuda_runtime.h>
#include <cuda_bf16.h>
#include <cstdint>

// HungarianMatcher cost computation, block-diagonal only.
// Shapes: BS=16, Q=1000, NC=80, T=100, NI=8
// Output: C_diag (BS,Q,T) followed by ioa_diag (BS,Q,NI), f32.
//
// Phase 1: dense (2*focal + 2) table for the block's QPB x NC tile (coalesced,
//          5 passes, refactored: cost2 = r^2*(0.5*e^2*L - 1.5*(x+L)) + 2);
//          raw pred boxes to smem; ioa lanes finish their output here.
// Phase 2: C-only hot loop: 2 LDS + short FFMA chain + 1 MUFU rcp + STG.
// NOTE: no manual software pipelining — at a 34-reg budget ptxas schedules
// the unrolled in-loop LDS better than a hand-rotated prefetch (R16 evidence:
// carried float4 rotation cost +15% instructions and +45% time).

#define BSZ 16
#define QN  1000
#define NC  80
#define TN  100
#define NIN 8
#define QPB 8    // q rows per block; 125 blocks cover Q=1000 exactly

// single-MUFU approximate reciprocal (~1 ulp; tolerance is 1e-3)
__device__ __forceinline__ float frcp(float x) {
    float y;
    asm("rcp.approx.ftz.f32 %0, %1;" : "=f"(y) : "f"(x));
    return y;
}
__device__ __forceinline__ float flg2(float x) {
    float y;
    asm("lg2.approx.ftz.f32 %0, %1;" : "=f"(y) : "f"(x));
    return y;
}
// streaming store (evict-first): outputs are write-once, never re-read
__device__ __forceinline__ void stcs(float* p, float v) {
    asm volatile("st.global.cs.f32 [%0], %1;" :: "l"(p), "f"(v) : "memory");
}

__global__ __launch_bounds__(128, 15)
void matcher_kernel(const float* __restrict__ logits,
                    const float* __restrict__ pboxes,
                    const float* __restrict__ tboxes,
                    const float* __restrict__ iboxes,
                    const float* __restrict__ img,
                    const float* __restrict__ img_tgt,
                    const int*   __restrict__ tids,
                    float* __restrict__ outC,
                    float* __restrict__ outIoa)
{
    __shared__ float  scc[QPB * NC];   // 2*focal cost + 2, [q_local][class]
    __shared__ float4 spq[QPB];        // raw pred boxes

    const int b    = blockIdx.y;
    const int q0   = blockIdx.x * QPB;
    const int lane = threadIdx.x;   // 0..99 -> targets, 100..107 -> ign boxes

    const bool isC   = (lane < TN);
    const bool isIoa = (lane >= TN) && (lane < TN + NIN);

    const float* pbox_base = pboxes + (size_t)(b * QN + q0) * 4;

    // ---------------- phase 1a: dense focal table (all lanes) ---------------
    // p = r = 1/(1+e), 1-p = e*r, L = log(1+e) = lg2(1+e)*ln2
    // cost2 = 2*(pos-neg)+2 = r^2*(0.5*e^2*L - 1.5*(x+L)) + 2
    {
        const float* gl = logits + (size_t)(b * QN + q0) * NC;
        #pragma unroll
        for (int k = 0; k < (QPB * NC) / 128; ++k) {      // exactly 5 passes
            const int idx   = k * 128 + lane;
            const float x   = __ldg(gl + idx);            // fully coalesced
            const float e   = __expf(-x);                 // mul + ex2
            const float s   = 1.f + e;
            const float r   = frcp(s);
            const float lam = flg2(s);
            const float t   = e * e;
            const float a   = t * lam;                    // e^2 * lg2(s)
            const float u   = fmaf(lam, 0.69314718f, x);  // x + L
            const float v   = -1.5f * u;
            const float inner = fmaf(a, 0.34657359f, v);  // 0.5*ln2*a - 1.5u
            const float r2  = r * r;
            scc[idx] = fmaf(r2, inner, 2.f);
        }
    }

    // ---------------- phase 1b: raw pred boxes to smem (lanes 0..QPB-1) -----
    if (lane < QPB) {
        spq[lane] = *reinterpret_cast<const float4*>(pbox_base + lane * 4);
    }

    // ---------------- ioa lanes: full output, straight from gmem ------------
    if (isIoa) {
        const int ii = b * NIN + (lane - TN);
        const float4 ib = *reinterpret_cast<const float4*>(iboxes + ii * 4);
        float* oI = outIoa + (size_t)(b * QN + q0) * NIN + (lane - TN);
        #pragma unroll
        for (int i = 0; i < QPB; ++i) {
            const float4 pb = *reinterpret_cast<const float4*>(pbox_base + i * 4);
            const float ixw = fminf(pb.z, ib.z) - fmaxf(pb.x, ib.x);
            const float iyw = fminf(pb.w, ib.w) - fmaxf(pb.y, ib.y);
            const float inter = fmaxf(ixw, 0.f) * fmaxf(iyw, 0.f);
            const float parea = (pb.z - pb.x) * (pb.w - pb.y);
            stcs(oI + i * NIN, inter * frcp(parea));
        }
    }

    // ---------------- per-lane uniform + target data ------------------------
    // i0..i3 = 5 / img. image_size_xyxy_tgt carries the same [W,H,W,H] per
    // row as image_size_xyxy, so the target normalization reuses i0..i3.
    const float* im = img + b * 4;
    const float i0 = 5.f * frcp(im[0]);
    const float i1 = 5.f * frcp(im[1]);
    const float i2 = 5.f * frcp(im[2]);
    const float i3 = 5.f * frcp(im[3]);

    float tx0 = 0.f, ty0 = 0.f, tx1 = 0.f, ty1 = 0.f;
    float tn0 = 0.f, tn1 = 0.f, tn2 = 0.f, tn3 = 0.f;   // 5 * normalized tgt
    float tw = 0.f, th = 0.f;
    const float* sccls = scc;   // per-lane gather base (scc + cls)

    if (isC) {
        const int ti = b * TN + lane;
        const float4 tb = *reinterpret_cast<const float4*>(tboxes + ti * 4);
        tx0 = tb.x; ty0 = tb.y; tx1 = tb.z; ty1 = tb.w;
        tn0 = tx0 * i0;
        tn1 = ty0 * i1;
        tn2 = tx1 * i2;
        tn3 = ty1 * i3;
        tw = tx1 - tx0;
        th = ty1 - ty0;
        sccls = scc + tids[ti];
    }

    __syncthreads();

    // ---------------- phase 2: C-only hot loop ------------------------------
    float* outC_lane = outC + (size_t)(b * QN + q0) * TN + lane;

    if (isC) {
        #pragma unroll
        for (int i = 0; i < QPB; ++i) {
            const float4 pb = spq[i];                     // LDS.128 broadcast
            const float cc2 = sccls[i * NC];              // class gather (imm offs)
            const float px0 = pb.x, py0 = pb.y, px1 = pb.z, py1 = pb.w;
            const float pw = px1 - px0;
            const float ph = py1 - py0;

            // 5 * L1 bbox cost: |px*ik - tnk| via FFMA, abs-modifier adds
            const float d0 = fmaf(px0, i0, -tn0);
            const float d1 = fmaf(py0, i1, -tn1);
            const float d2 = fmaf(px1, i2, -tn2);
            const float d3 = fmaf(py1, i3, -tn3);
            const float cb5 = (fabsf(d0) + fabsf(d1)) + (fabsf(d2) + fabsf(d3));

            // intersection widths (4 FMNMX + 2 clamps)
            const float ixw = fminf(px1, tx1) - fmaxf(px0, tx0);
            const float iyw = fminf(py1, ty1) - fmaxf(py0, ty0);
            const float inter = fmaxf(ixw, 0.f) * fmaxf(iyw, 0.f);

            // enclosure via min+max identity (no FMNMX, no clamps)
            const float exw = (pw + tw) - ixw;
            const float eyw = (ph + th) - iyw;
            const float enc = exw * eyw;

            // uni = parea + tarea - inter (both areas as FFMA)
            const float uni = fmaf(tw, th, fmaf(pw, ph, -inter));

            // C = cb5 + cc' - 2*(inter*enc + uni^2)/(uni*enc)
            const float M   = fmaf(uni, uni, inter * enc);
            const float n2r = -2.f * frcp(uni * enc);
            stcs(outC_lane + i * TN, fmaf(M, n2r, cb5 + cc2));
        }
    }
}

extern "C" void kernel_launch(void* const* d_in, const int* in_sizes, int n_in,
                              void* d_out, int out_size)
{
    const float* logits  = (const float*)d_in[0];
    const float* pboxes  = (const float*)d_in[1];
    const float* tboxes  = (const float*)d_in[2];
    const float* iboxes  = (const float*)d_in[3];
    const float* img     = (const float*)d_in[4];
    const float* img_tgt = (const float*)d_in[5];
    const int*   tids    = (const int*)d_in[6];

    float* outC   = (float*)d_out;
    float* outIoa = (float*)d_out + (size_t)BSZ * QN * TN;

    dim3 grid(QN / QPB, BSZ);   // 125 x 16 = 2000 blocks
    matcher_kernel<<<grid, 128>>>(logits, pboxes, tboxes, iboxes,
                                  img, img_tgt, tids, outC, outIoa);
}